// round 1
// baseline (speedup 1.0000x reference)
#include <cuda_runtime.h>
#include <cstdint>
#include <cstddef>

#define NN 2048
#define BB 8
#define TT 12
#define DD 64
#define BD  (BB*DD)        // 512
#define BTD (BB*TT*DD)     // 6144
#define ROWS (NN*BB)       // 16384

// ---------------- scratch (device globals; no allocs allowed) ----------------
__device__ float g_S2 [(size_t)NN*NN];    // 2A^2 - I
__device__ float g_xT [(size_t)NN*BTD];   // x transposed to [n][b][t][d]
__device__ float g_xd1[(size_t)NN*BTD];   // A  @ xT
__device__ float g_xd2[(size_t)NN*BTD];   // S2 @ xT
__device__ float g_h  [(size_t)NN*BD];    // state  [n][b][d]
__device__ float g_hd1[(size_t)NN*BD];
__device__ float g_hd2[(size_t)NN*BD];
__device__ float g_g  [(size_t)NN*BD];    // z * h
__device__ float g_gd1[(size_t)NN*BD];
__device__ float g_gd2[(size_t)NN*BD];
__device__ float g_r  [(size_t)NN*BD];    // r gate

// ---------------- layout helpers ----------------
// x (input) : [b][t][n][d]
// xT / xd*  : row = n*BB+b, within row: [t][d] (stride TT*DD per row)
// h / hd* / g / gd* / r : row = n*BB+b, within row: [d] (stride DD)

// ---------------- transpose x -> xT ----------------
__global__ void transpose_x_kernel(const float* __restrict__ x) {
    size_t i = (size_t)blockIdx.x * 256 + threadIdx.x;
    const size_t total = (size_t)BB*TT*NN*DD;
    if (i >= total) return;
    int d = (int)(i & 63);
    size_t q = i >> 6;           // (b*TT+t)*NN + n
    int n = (int)(q & (NN-1));
    q >>= 11;                    // b*TT + t
    int t = (int)(q % TT);
    int b = (int)(q / TT);
    g_xT[(((size_t)n*BB + b)*TT + t)*DD + d] = x[i];
}

__global__ void init_h_kernel(const float* __restrict__ h0) {
    size_t i = (size_t)blockIdx.x * 256 + threadIdx.x;   // over [b][n][d]
    const size_t total = (size_t)BB*NN*DD;
    if (i >= total) return;
    int d = (int)(i & 63);
    size_t q = i >> 6;           // b*NN + n
    int n = (int)(q & (NN-1));
    int b = (int)(q >> 11);
    g_h[((size_t)n*BB + b)*DD + d] = h0[i];
}

__global__ void write_last_kernel(float* __restrict__ out_last) {
    size_t i = (size_t)blockIdx.x * 256 + threadIdx.x;   // over [b][n][d]
    const size_t total = (size_t)BB*NN*DD;
    if (i >= total) return;
    int d = (int)(i & 63);
    size_t q = i >> 6;
    int n = (int)(q & (NN-1));
    int b = (int)(q >> 11);
    out_last[i] = g_h[((size_t)n*BB + b)*DD + d];
}

// ---------------- generic SGEMM: C[M,N] = A[M,K] @ B[K,N] ----------------
// MODE 0: plain   MODE 1: C = 2*acc - I  (for S2)
// BM=BN=64, BK=16, 128 threads, thread tile 8x4. All dims divide evenly.
template<int MODE>
__global__ __launch_bounds__(128)
void sgemm64(const float* __restrict__ A, const float* __restrict__ B,
             float* __restrict__ C, int M, int N, int K) {
    __shared__ float As[16][64];
    __shared__ float Bs[16][64];
    int tid  = threadIdx.x;
    int row0 = blockIdx.y << 6;
    int col0 = blockIdx.x << 6;
    int ty = tid >> 4;      // 0..7  -> rows ty*8
    int tx = tid & 15;      // 0..15 -> cols tx*4
    float acc[8][4] = {};

    for (int k0 = 0; k0 < K; k0 += 16) {
        #pragma unroll
        for (int i = 0; i < 2; i++) {
            int c = tid + (i << 7);           // 0..255 float4 chunks of A tile
            int r = c >> 2, c4 = (c & 3) << 2;
            float4 v = *(const float4*)&A[(size_t)(row0 + r)*K + k0 + c4];
            As[c4+0][r] = v.x; As[c4+1][r] = v.y;
            As[c4+2][r] = v.z; As[c4+3][r] = v.w;
        }
        #pragma unroll
        for (int i = 0; i < 2; i++) {
            int c = tid + (i << 7);
            int r = c >> 4, c4 = (c & 15) << 2;
            *(float4*)&Bs[r][c4] = *(const float4*)&B[(size_t)(k0 + r)*N + col0 + c4];
        }
        __syncthreads();
        #pragma unroll
        for (int k = 0; k < 16; k++) {
            float4 a0 = *(const float4*)&As[k][ty << 3];
            float4 a1 = *(const float4*)&As[k][(ty << 3) + 4];
            float4 bv = *(const float4*)&Bs[k][tx << 2];
            float a[8] = {a0.x,a0.y,a0.z,a0.w,a1.x,a1.y,a1.z,a1.w};
            float b[4] = {bv.x,bv.y,bv.z,bv.w};
            #pragma unroll
            for (int ii = 0; ii < 8; ii++)
                #pragma unroll
                for (int jj = 0; jj < 4; jj++)
                    acc[ii][jj] += a[ii] * b[jj];
        }
        __syncthreads();
    }
    #pragma unroll
    for (int ii = 0; ii < 8; ii++) {
        int r = row0 + (ty << 3) + ii;
        int c = col0 + (tx << 2);
        float4 v;
        v.x = acc[ii][0]; v.y = acc[ii][1]; v.z = acc[ii][2]; v.w = acc[ii][3];
        if (MODE == 1) {
            v.x = 2.f*v.x - ((r == c+0) ? 1.f : 0.f);
            v.y = 2.f*v.y - ((r == c+1) ? 1.f : 0.f);
            v.z = 2.f*v.z - ((r == c+2) ? 1.f : 0.f);
            v.w = 2.f*v.w - ((r == c+3) ? 1.f : 0.f);
        }
        *(float4*)&C[(size_t)r*N + c] = v;
    }
}

// ---------------- gate: zr = sigmoid([f6]@Wg + bg); g = z*h; store r ----------
// rows = n*BB+b (16384), cols = 128. K = 384 in 12 chunks of 32.
// chunk source order MUST match W_gate [K=3][2D=128][128] flattening:
//   k0:[x_t | h], k1:[xd1 | hd1], k2:[xd2 | hd2]
__global__ __launch_bounds__(256)
void gate_kernel(const float* __restrict__ Wg, const float* __restrict__ bg, int t) {
    __shared__ float Fs[32][68];    // [k][row], padded
    __shared__ float Ws[32][128];
    int tid  = threadIdx.x;
    int row0 = blockIdx.x << 6;     // 64 rows per block
    int ty = tid >> 4;              // 0..15 -> rows ty*4
    int tx = tid & 15;              // 0..15 -> cols tx*8
    float acc[4][8] = {};

    for (int kc = 0; kc < 12; kc++) {
        int s    = kc >> 1;
        int koff = (kc & 1) << 5;
        const float* src; size_t stride;
        switch (s) {
            case 0: src = g_xT  + (size_t)t*DD; stride = (size_t)TT*DD; break;
            case 1: src = g_h;                  stride = DD;            break;
            case 2: src = g_xd1 + (size_t)t*DD; stride = (size_t)TT*DD; break;
            case 3: src = g_hd1;                stride = DD;            break;
            case 4: src = g_xd2 + (size_t)t*DD; stride = (size_t)TT*DD; break;
            default:src = g_hd2;                stride = DD;            break;
        }
        #pragma unroll
        for (int i = 0; i < 8; i++) {
            int c = tid + (i << 8);           // 0..2047
            int k = c & 31, r = c >> 5;
            Fs[k][r] = src[(size_t)(row0 + r)*stride + koff + k];
        }
        #pragma unroll
        for (int i = 0; i < 4; i++) {
            int c  = tid + (i << 8);          // float4 id 0..1023
            int k  = c >> 5, o4 = (c & 31) << 2;
            *(float4*)&Ws[k][o4] = *(const float4*)&Wg[(size_t)(kc*32 + k)*128 + o4];
        }
        __syncthreads();
        #pragma unroll
        for (int k = 0; k < 32; k++) {
            float4 av = *(const float4*)&Fs[k][ty << 2];
            float4 w0 = *(const float4*)&Ws[k][tx << 3];
            float4 w1 = *(const float4*)&Ws[k][(tx << 3) + 4];
            float a[4] = {av.x, av.y, av.z, av.w};
            float w[8] = {w0.x,w0.y,w0.z,w0.w,w1.x,w1.y,w1.z,w1.w};
            #pragma unroll
            for (int ii = 0; ii < 4; ii++)
                #pragma unroll
                for (int jj = 0; jj < 8; jj++)
                    acc[ii][jj] += a[ii] * w[jj];
        }
        __syncthreads();
    }
    #pragma unroll
    for (int ii = 0; ii < 4; ii++) {
        int r = row0 + (ty << 2) + ii;
        #pragma unroll
        for (int jj = 0; jj < 8; jj++) {
            int o = (tx << 3) + jj;
            float v  = acc[ii][jj] + bg[o];
            float sg = 1.f / (1.f + expf(-v));
            if (o < 64) g_g[(size_t)r*DD + o]        = sg * g_h[(size_t)r*DD + o];
            else        g_r[(size_t)r*DD + (o - 64)] = sg;
        }
    }
}

// ---------------- cand: hc = tanh([f6]@Wc + bc); GRU update; residual out ----
// chunk order: k0:[x_t | g], k1:[xd1 | gd1], k2:[xd2 | gd2]
__global__ __launch_bounds__(256)
void cand_kernel(const float* __restrict__ Wc, const float* __restrict__ bc,
                 const float* __restrict__ x, float* __restrict__ out, int t) {
    __shared__ float Fs[32][68];
    __shared__ float Ws[32][64];
    int tid  = threadIdx.x;
    int row0 = blockIdx.x << 6;
    int ty = tid >> 4;              // rows ty*4
    int tx = tid & 15;              // cols tx*4
    float acc[4][4] = {};

    for (int kc = 0; kc < 12; kc++) {
        int s    = kc >> 1;
        int koff = (kc & 1) << 5;
        const float* src; size_t stride;
        switch (s) {
            case 0: src = g_xT  + (size_t)t*DD; stride = (size_t)TT*DD; break;
            case 1: src = g_g;                  stride = DD;            break;
            case 2: src = g_xd1 + (size_t)t*DD; stride = (size_t)TT*DD; break;
            case 3: src = g_gd1;                stride = DD;            break;
            case 4: src = g_xd2 + (size_t)t*DD; stride = (size_t)TT*DD; break;
            default:src = g_gd2;                stride = DD;            break;
        }
        #pragma unroll
        for (int i = 0; i < 8; i++) {
            int c = tid + (i << 8);
            int k = c & 31, r = c >> 5;
            Fs[k][r] = src[(size_t)(row0 + r)*stride + koff + k];
        }
        #pragma unroll
        for (int i = 0; i < 2; i++) {
            int c  = tid + (i << 8);          // float4 id 0..511
            int k  = c >> 4, o4 = (c & 15) << 2;
            *(float4*)&Ws[k][o4] = *(const float4*)&Wc[(size_t)(kc*32 + k)*64 + o4];
        }
        __syncthreads();
        #pragma unroll
        for (int k = 0; k < 32; k++) {
            float4 av = *(const float4*)&Fs[k][ty << 2];
            float4 wv = *(const float4*)&Ws[k][tx << 2];
            float a[4] = {av.x, av.y, av.z, av.w};
            float w[4] = {wv.x, wv.y, wv.z, wv.w};
            #pragma unroll
            for (int ii = 0; ii < 4; ii++)
                #pragma unroll
                for (int jj = 0; jj < 4; jj++)
                    acc[ii][jj] += a[ii] * w[jj];
        }
        __syncthreads();
    }
    #pragma unroll
    for (int ii = 0; ii < 4; ii++) {
        int r = row0 + (ty << 2) + ii;
        int n = r >> 3, b = r & 7;
        size_t xbase = (((size_t)b*TT + t)*NN + n)*DD;
        #pragma unroll
        for (int jj = 0; jj < 4; jj++) {
            int o = (tx << 2) + jj;
            float hc = tanhf(acc[ii][jj] + bc[o]);
            size_t idx = (size_t)r*DD + o;
            float rg  = g_r[idx];
            float h0v = g_h[idx];
            float hn  = rg * h0v + (1.f - rg) * hc;
            g_h[idx] = hn;                       // in-place: element owned by this thread
            out[xbase + o] = x[xbase + o] + hn;  // residual
        }
    }
}

// ---------------- launch ----------------
extern "C" void kernel_launch(void* const* d_in, const int* in_sizes, int n_in,
                              void* d_out, int out_size) {
    const float* x   = (const float*)d_in[0];
    const float* h0  = (const float*)d_in[1];
    const float* adj = (const float*)d_in[2];
    const float* Wg  = (const float*)d_in[3];
    const float* bg  = (const float*)d_in[4];
    const float* Wc  = (const float*)d_in[5];
    const float* bc  = (const float*)d_in[6];
    float* out = (float*)d_out;

    void *pS2, *pxT, *pxd1, *pxd2, *ph, *phd1, *phd2, *pg, *pgd1, *pgd2;
    cudaGetSymbolAddress(&pS2,  g_S2);
    cudaGetSymbolAddress(&pxT,  g_xT);
    cudaGetSymbolAddress(&pxd1, g_xd1);
    cudaGetSymbolAddress(&pxd2, g_xd2);
    cudaGetSymbolAddress(&ph,   g_h);
    cudaGetSymbolAddress(&phd1, g_hd1);
    cudaGetSymbolAddress(&phd2, g_hd2);
    cudaGetSymbolAddress(&pg,   g_g);
    cudaGetSymbolAddress(&pgd1, g_gd1);
    cudaGetSymbolAddress(&pgd2, g_gd2);

    const size_t total_x = (size_t)BB*TT*NN*DD;     // 12,582,912
    const size_t total_h = (size_t)BB*NN*DD;        // 1,048,576

    transpose_x_kernel<<<(int)((total_x + 255)/256), 256>>>(x);
    init_h_kernel<<<(int)((total_h + 255)/256), 256>>>(h0);

    // S2 = 2*A@A - I
    sgemm64<1><<<dim3(NN/64, NN/64), 128>>>(adj, adj, (float*)pS2, NN, NN, NN);
    // x diffusions (whole sequence at once)
    sgemm64<0><<<dim3(BTD/64, NN/64), 128>>>(adj,          (const float*)pxT, (float*)pxd1, NN, BTD, NN);
    sgemm64<0><<<dim3(BTD/64, NN/64), 128>>>((float*)pS2,  (const float*)pxT, (float*)pxd2, NN, BTD, NN);

    for (int t = 0; t < TT; t++) {
        sgemm64<0><<<dim3(BD/64, NN/64), 128>>>(adj,         (const float*)ph, (float*)phd1, NN, BD, NN);
        sgemm64<0><<<dim3(BD/64, NN/64), 128>>>((float*)pS2, (const float*)ph, (float*)phd2, NN, BD, NN);
        gate_kernel<<<ROWS/64, 256>>>(Wg, bg, t);
        sgemm64<0><<<dim3(BD/64, NN/64), 128>>>(adj,         (const float*)pg, (float*)pgd1, NN, BD, NN);
        sgemm64<0><<<dim3(BD/64, NN/64), 128>>>((float*)pS2, (const float*)pg, (float*)pgd2, NN, BD, NN);
        cand_kernel<<<ROWS/64, 256>>>(Wc, bc, x, out, t);
    }

    write_last_kernel<<<(int)((total_h + 255)/256), 256>>>(out + total_x);
}

// round 2
// speedup vs baseline: 1.0006x; 1.0006x over previous
#include <cuda_runtime.h>
#include <cstdint>
#include <cstddef>

#define NN 2048
#define BB 8
#define TT 12
#define DD 64
#define BD  (BB*DD)        // 512
#define BTD (BB*TT*DD)     // 6144
#define ROWS (NN*BB)       // 16384

// ---------------- scratch (device globals; no allocs allowed) ----------------
__device__ float g_S2 [(size_t)NN*NN];    // 2A^2 - I
__device__ float g_xT [(size_t)NN*BTD];   // x transposed to [n][b][t][d]
__device__ float g_xd1[(size_t)NN*BTD];   // A  @ xT
__device__ float g_xd2[(size_t)NN*BTD];   // S2 @ xT
__device__ float g_h  [(size_t)NN*BD];    // state  [n][b][d]
__device__ float g_hd1[(size_t)NN*BD];
__device__ float g_hd2[(size_t)NN*BD];
__device__ float g_g  [(size_t)NN*BD];    // z * h
__device__ float g_gd1[(size_t)NN*BD];
__device__ float g_gd2[(size_t)NN*BD];
__device__ float g_r  [(size_t)NN*BD];    // r gate

// ---------------- layout helpers ----------------
// x (input) : [b][t][n][d]
// xT / xd*  : row = n*BB+b, within row: [t][d] (stride TT*DD per row)
// h / hd* / g / gd* / r : row = n*BB+b, within row: [d] (stride DD)

// ---------------- transpose x -> xT ----------------
__global__ void transpose_x_kernel(const float* __restrict__ x) {
    size_t i = (size_t)blockIdx.x * 256 + threadIdx.x;
    const size_t total = (size_t)BB*TT*NN*DD;
    if (i >= total) return;
    int d = (int)(i & 63);
    size_t q = i >> 6;           // (b*TT+t)*NN + n
    int n = (int)(q & (NN-1));
    q >>= 11;                    // b*TT + t
    int t = (int)(q % TT);
    int b = (int)(q / TT);
    g_xT[(((size_t)n*BB + b)*TT + t)*DD + d] = x[i];
}

__global__ void init_h_kernel(const float* __restrict__ h0) {
    size_t i = (size_t)blockIdx.x * 256 + threadIdx.x;   // over [b][n][d]
    const size_t total = (size_t)BB*NN*DD;
    if (i >= total) return;
    int d = (int)(i & 63);
    size_t q = i >> 6;           // b*NN + n
    int n = (int)(q & (NN-1));
    int b = (int)(q >> 11);
    g_h[((size_t)n*BB + b)*DD + d] = h0[i];
}

__global__ void write_last_kernel(float* __restrict__ out_last) {
    size_t i = (size_t)blockIdx.x * 256 + threadIdx.x;   // over [b][n][d]
    const size_t total = (size_t)BB*NN*DD;
    if (i >= total) return;
    int d = (int)(i & 63);
    size_t q = i >> 6;
    int n = (int)(q & (NN-1));
    int b = (int)(q >> 11);
    out_last[i] = g_h[((size_t)n*BB + b)*DD + d];
}

// ---------------- generic SGEMM: C[M,N] = A[M,K] @ B[K,N] ----------------
// MODE 0: plain   MODE 1: C = 2*acc - I  (for S2)
// BM=BN=64, BK=16, 128 threads, thread tile 8x4. All dims divide evenly.
template<int MODE>
__global__ __launch_bounds__(128)
void sgemm64(const float* __restrict__ A, const float* __restrict__ B,
             float* __restrict__ C, int M, int N, int K) {
    __shared__ float As[16][64];
    __shared__ float Bs[16][64];
    int tid  = threadIdx.x;
    int row0 = blockIdx.y << 6;
    int col0 = blockIdx.x << 6;
    int ty = tid >> 4;      // 0..7  -> rows ty*8
    int tx = tid & 15;      // 0..15 -> cols tx*4
    float acc[8][4] = {};

    for (int k0 = 0; k0 < K; k0 += 16) {
        #pragma unroll
        for (int i = 0; i < 2; i++) {
            int c = tid + (i << 7);           // 0..255 float4 chunks of A tile
            int r = c >> 2, c4 = (c & 3) << 2;
            float4 v = *(const float4*)&A[(size_t)(row0 + r)*K + k0 + c4];
            As[c4+0][r] = v.x; As[c4+1][r] = v.y;
            As[c4+2][r] = v.z; As[c4+3][r] = v.w;
        }
        #pragma unroll
        for (int i = 0; i < 2; i++) {
            int c = tid + (i << 7);
            int r = c >> 4, c4 = (c & 15) << 2;
            *(float4*)&Bs[r][c4] = *(const float4*)&B[(size_t)(k0 + r)*N + col0 + c4];
        }
        __syncthreads();
        #pragma unroll
        for (int k = 0; k < 16; k++) {
            float4 a0 = *(const float4*)&As[k][ty << 3];
            float4 a1 = *(const float4*)&As[k][(ty << 3) + 4];
            float4 bv = *(const float4*)&Bs[k][tx << 2];
            float a[8] = {a0.x,a0.y,a0.z,a0.w,a1.x,a1.y,a1.z,a1.w};
            float b[4] = {bv.x,bv.y,bv.z,bv.w};
            #pragma unroll
            for (int ii = 0; ii < 8; ii++)
                #pragma unroll
                for (int jj = 0; jj < 4; jj++)
                    acc[ii][jj] += a[ii] * b[jj];
        }
        __syncthreads();
    }
    #pragma unroll
    for (int ii = 0; ii < 8; ii++) {
        int r = row0 + (ty << 3) + ii;
        int c = col0 + (tx << 2);
        float4 v;
        v.x = acc[ii][0]; v.y = acc[ii][1]; v.z = acc[ii][2]; v.w = acc[ii][3];
        if (MODE == 1) {
            v.x = 2.f*v.x - ((r == c+0) ? 1.f : 0.f);
            v.y = 2.f*v.y - ((r == c+1) ? 1.f : 0.f);
            v.z = 2.f*v.z - ((r == c+2) ? 1.f : 0.f);
            v.w = 2.f*v.w - ((r == c+3) ? 1.f : 0.f);
        }
        *(float4*)&C[(size_t)r*N + c] = v;
    }
}

// ---------------- gate: zr = sigmoid([f6]@Wg + bg); g = z*h; store r ----------
// rows = n*BB+b (16384), cols = 128. K = 384 in 12 chunks of 32.
// chunk source order MUST match W_gate [K=3][2D=128][128] flattening:
//   k0:[x_t | h], k1:[xd1 | hd1], k2:[xd2 | hd2]
__global__ __launch_bounds__(256)
void gate_kernel(const float* __restrict__ Wg, const float* __restrict__ bg, int t) {
    __shared__ float Fs[32][68];    // [k][row], padded
    __shared__ float Ws[32][128];
    int tid  = threadIdx.x;
    int row0 = blockIdx.x << 6;     // 64 rows per block
    int ty = tid >> 4;              // 0..15 -> rows ty*4
    int tx = tid & 15;              // 0..15 -> cols tx*8
    float acc[4][8] = {};

    for (int kc = 0; kc < 12; kc++) {
        int s    = kc >> 1;
        int koff = (kc & 1) << 5;
        const float* src; size_t stride;
        switch (s) {
            case 0: src = g_xT  + (size_t)t*DD; stride = (size_t)TT*DD; break;
            case 1: src = g_h;                  stride = DD;            break;
            case 2: src = g_xd1 + (size_t)t*DD; stride = (size_t)TT*DD; break;
            case 3: src = g_hd1;                stride = DD;            break;
            case 4: src = g_xd2 + (size_t)t*DD; stride = (size_t)TT*DD; break;
            default:src = g_hd2;                stride = DD;            break;
        }
        #pragma unroll
        for (int i = 0; i < 8; i++) {
            int c = tid + (i << 8);           // 0..2047
            int k = c & 31, r = c >> 5;
            Fs[k][r] = src[(size_t)(row0 + r)*stride + koff + k];
        }
        #pragma unroll
        for (int i = 0; i < 4; i++) {
            int c  = tid + (i << 8);          // float4 id 0..1023
            int k  = c >> 5, o4 = (c & 31) << 2;
            *(float4*)&Ws[k][o4] = *(const float4*)&Wg[(size_t)(kc*32 + k)*128 + o4];
        }
        __syncthreads();
        #pragma unroll
        for (int k = 0; k < 32; k++) {
            float4 av = *(const float4*)&Fs[k][ty << 2];
            float4 w0 = *(const float4*)&Ws[k][tx << 3];
            float4 w1 = *(const float4*)&Ws[k][(tx << 3) + 4];
            float a[4] = {av.x, av.y, av.z, av.w};
            float w[8] = {w0.x,w0.y,w0.z,w0.w,w1.x,w1.y,w1.z,w1.w};
            #pragma unroll
            for (int ii = 0; ii < 4; ii++)
                #pragma unroll
                for (int jj = 0; jj < 8; jj++)
                    acc[ii][jj] += a[ii] * w[jj];
        }
        __syncthreads();
    }
    #pragma unroll
    for (int ii = 0; ii < 4; ii++) {
        int r = row0 + (ty << 2) + ii;
        #pragma unroll
        for (int jj = 0; jj < 8; jj++) {
            int o = (tx << 3) + jj;
            float v  = acc[ii][jj] + bg[o];
            float sg = 1.f / (1.f + expf(-v));
            if (o < 64) g_g[(size_t)r*DD + o]        = sg * g_h[(size_t)r*DD + o];
            else        g_r[(size_t)r*DD + (o - 64)] = sg;
        }
    }
}

// ---------------- cand: hc = tanh([f6]@Wc + bc); GRU update; residual out ----
// chunk order: k0:[x_t | g], k1:[xd1 | gd1], k2:[xd2 | gd2]
__global__ __launch_bounds__(256)
void cand_kernel(const float* __restrict__ Wc, const float* __restrict__ bc,
                 const float* __restrict__ x, float* __restrict__ out, int t) {
    __shared__ float Fs[32][68];
    __shared__ float Ws[32][64];
    int tid  = threadIdx.x;
    int row0 = blockIdx.x << 6;
    int ty = tid >> 4;              // rows ty*4
    int tx = tid & 15;              // cols tx*4
    float acc[4][4] = {};

    for (int kc = 0; kc < 12; kc++) {
        int s    = kc >> 1;
        int koff = (kc & 1) << 5;
        const float* src; size_t stride;
        switch (s) {
            case 0: src = g_xT  + (size_t)t*DD; stride = (size_t)TT*DD; break;
            case 1: src = g_g;                  stride = DD;            break;
            case 2: src = g_xd1 + (size_t)t*DD; stride = (size_t)TT*DD; break;
            case 3: src = g_gd1;                stride = DD;            break;
            case 4: src = g_xd2 + (size_t)t*DD; stride = (size_t)TT*DD; break;
            default:src = g_gd2;                stride = DD;            break;
        }
        #pragma unroll
        for (int i = 0; i < 8; i++) {
            int c = tid + (i << 8);
            int k = c & 31, r = c >> 5;
            Fs[k][r] = src[(size_t)(row0 + r)*stride + koff + k];
        }
        #pragma unroll
        for (int i = 0; i < 2; i++) {
            int c  = tid + (i << 8);          // float4 id 0..511
            int k  = c >> 4, o4 = (c & 15) << 2;
            *(float4*)&Ws[k][o4] = *(const float4*)&Wc[(size_t)(kc*32 + k)*64 + o4];
        }
        __syncthreads();
        #pragma unroll
        for (int k = 0; k < 32; k++) {
            float4 av = *(const float4*)&Fs[k][ty << 2];
            float4 wv = *(const float4*)&Ws[k][tx << 2];
            float a[4] = {av.x, av.y, av.z, av.w};
            float w[4] = {wv.x, wv.y, wv.z, wv.w};
            #pragma unroll
            for (int ii = 0; ii < 4; ii++)
                #pragma unroll
                for (int jj = 0; jj < 4; jj++)
                    acc[ii][jj] += a[ii] * w[jj];
        }
        __syncthreads();
    }
    #pragma unroll
    for (int ii = 0; ii < 4; ii++) {
        int r = row0 + (ty << 2) + ii;
        int n = r >> 3, b = r & 7;
        size_t xbase = (((size_t)b*TT + t)*NN + n)*DD;
        #pragma unroll
        for (int jj = 0; jj < 4; jj++) {
            int o = (tx << 2) + jj;
            float hc = tanhf(acc[ii][jj] + bc[o]);
            size_t idx = (size_t)r*DD + o;
            float rg  = g_r[idx];
            float h0v = g_h[idx];
            float hn  = rg * h0v + (1.f - rg) * hc;
            g_h[idx] = hn;                       // in-place: element owned by this thread
            out[xbase + o] = x[xbase + o] + hn;  // residual
        }
    }
}

// ---------------- launch ----------------
extern "C" void kernel_launch(void* const* d_in, const int* in_sizes, int n_in,
                              void* d_out, int out_size) {
    const float* x   = (const float*)d_in[0];
    const float* h0  = (const float*)d_in[1];
    const float* adj = (const float*)d_in[2];
    const float* Wg  = (const float*)d_in[3];
    const float* bg  = (const float*)d_in[4];
    const float* Wc  = (const float*)d_in[5];
    const float* bc  = (const float*)d_in[6];
    float* out = (float*)d_out;

    void *pS2, *pxT, *pxd1, *pxd2, *ph, *phd1, *phd2, *pg, *pgd1, *pgd2;
    cudaGetSymbolAddress(&pS2,  g_S2);
    cudaGetSymbolAddress(&pxT,  g_xT);
    cudaGetSymbolAddress(&pxd1, g_xd1);
    cudaGetSymbolAddress(&pxd2, g_xd2);
    cudaGetSymbolAddress(&ph,   g_h);
    cudaGetSymbolAddress(&phd1, g_hd1);
    cudaGetSymbolAddress(&phd2, g_hd2);
    cudaGetSymbolAddress(&pg,   g_g);
    cudaGetSymbolAddress(&pgd1, g_gd1);
    cudaGetSymbolAddress(&pgd2, g_gd2);

    const size_t total_x = (size_t)BB*TT*NN*DD;     // 12,582,912
    const size_t total_h = (size_t)BB*NN*DD;        // 1,048,576

    transpose_x_kernel<<<(int)((total_x + 255)/256), 256>>>(x);
    init_h_kernel<<<(int)((total_h + 255)/256), 256>>>(h0);

    // S2 = 2*A@A - I
    sgemm64<1><<<dim3(NN/64, NN/64), 128>>>(adj, adj, (float*)pS2, NN, NN, NN);
    // x diffusions (whole sequence at once)
    sgemm64<0><<<dim3(BTD/64, NN/64), 128>>>(adj,          (const float*)pxT, (float*)pxd1, NN, BTD, NN);
    sgemm64<0><<<dim3(BTD/64, NN/64), 128>>>((float*)pS2,  (const float*)pxT, (float*)pxd2, NN, BTD, NN);

    for (int t = 0; t < TT; t++) {
        sgemm64<0><<<dim3(BD/64, NN/64), 128>>>(adj,         (const float*)ph, (float*)phd1, NN, BD, NN);
        sgemm64<0><<<dim3(BD/64, NN/64), 128>>>((float*)pS2, (const float*)ph, (float*)phd2, NN, BD, NN);
        gate_kernel<<<ROWS/64, 256>>>(Wg, bg, t);
        sgemm64<0><<<dim3(BD/64, NN/64), 128>>>(adj,         (const float*)pg, (float*)pgd1, NN, BD, NN);
        sgemm64<0><<<dim3(BD/64, NN/64), 128>>>((float*)pS2, (const float*)pg, (float*)pgd2, NN, BD, NN);
        cand_kernel<<<ROWS/64, 256>>>(Wc, bc, x, out, t);
    }

    write_last_kernel<<<(int)((total_h + 255)/256), 256>>>(out + total_x);
}

// round 3
// speedup vs baseline: 1.0016x; 1.0010x over previous
#include <cuda_runtime.h>
#include <cstdint>
#include <cstddef>

#define NN 2048
#define BB 8
#define TT 12
#define DD 64
#define BD  (BB*DD)        // 512
#define BTD (BB*TT*DD)     // 6144
#define ROWS (NN*BB)       // 16384

// ---------------- scratch (device globals; no allocs allowed) ----------------
__device__ float g_S2 [(size_t)NN*NN];    // 2A^2 - I
__device__ float g_xT [(size_t)NN*BTD];   // x transposed to [n][b][t][d]
__device__ float g_xd1[(size_t)NN*BTD];   // A  @ xT
__device__ float g_xd2[(size_t)NN*BTD];   // S2 @ xT
__device__ float g_h  [(size_t)NN*BD];    // state  [n][b][d]
__device__ float g_hd1[(size_t)NN*BD];
__device__ float g_hd2[(size_t)NN*BD];
__device__ float g_g  [(size_t)NN*BD];    // z * h
__device__ float g_gd1[(size_t)NN*BD];
__device__ float g_gd2[(size_t)NN*BD];
__device__ float g_r  [(size_t)NN*BD];    // r gate

// ---------------- layout helpers ----------------
// x (input) : [b][t][n][d]
// xT / xd*  : row = n*BB+b, within row: [t][d] (stride TT*DD per row)
// h / hd* / g / gd* / r : row = n*BB+b, within row: [d] (stride DD)

// ---------------- transpose x -> xT ----------------
__global__ void transpose_x_kernel(const float* __restrict__ x) {
    size_t i = (size_t)blockIdx.x * 256 + threadIdx.x;
    const size_t total = (size_t)BB*TT*NN*DD;
    if (i >= total) return;
    int d = (int)(i & 63);
    size_t q = i >> 6;           // (b*TT+t)*NN + n
    int n = (int)(q & (NN-1));
    q >>= 11;                    // b*TT + t
    int t = (int)(q % TT);
    int b = (int)(q / TT);
    g_xT[(((size_t)n*BB + b)*TT + t)*DD + d] = x[i];
}

__global__ void init_h_kernel(const float* __restrict__ h0) {
    size_t i = (size_t)blockIdx.x * 256 + threadIdx.x;   // over [b][n][d]
    const size_t total = (size_t)BB*NN*DD;
    if (i >= total) return;
    int d = (int)(i & 63);
    size_t q = i >> 6;           // b*NN + n
    int n = (int)(q & (NN-1));
    int b = (int)(q >> 11);
    g_h[((size_t)n*BB + b)*DD + d] = h0[i];
}

__global__ void write_last_kernel(float* __restrict__ out_last) {
    size_t i = (size_t)blockIdx.x * 256 + threadIdx.x;   // over [b][n][d]
    const size_t total = (size_t)BB*NN*DD;
    if (i >= total) return;
    int d = (int)(i & 63);
    size_t q = i >> 6;
    int n = (int)(q & (NN-1));
    int b = (int)(q >> 11);
    out_last[i] = g_h[((size_t)n*BB + b)*DD + d];
}

// ---------------- generic SGEMM: C[M,N] = A[M,K] @ B[K,N] ----------------
// MODE 0: plain   MODE 1: C = 2*acc - I  (for S2)
// BM=BN=64, BK=16, 128 threads, thread tile 8x4. All dims divide evenly.
template<int MODE>
__global__ __launch_bounds__(128)
void sgemm64(const float* __restrict__ A, const float* __restrict__ B,
             float* __restrict__ C, int M, int N, int K) {
    __shared__ float As[16][64];
    __shared__ float Bs[16][64];
    int tid  = threadIdx.x;
    int row0 = blockIdx.y << 6;
    int col0 = blockIdx.x << 6;
    int ty = tid >> 4;      // 0..7  -> rows ty*8
    int tx = tid & 15;      // 0..15 -> cols tx*4
    float acc[8][4] = {};

    for (int k0 = 0; k0 < K; k0 += 16) {
        #pragma unroll
        for (int i = 0; i < 2; i++) {
            int c = tid + (i << 7);           // 0..255 float4 chunks of A tile
            int r = c >> 2, c4 = (c & 3) << 2;
            float4 v = *(const float4*)&A[(size_t)(row0 + r)*K + k0 + c4];
            As[c4+0][r] = v.x; As[c4+1][r] = v.y;
            As[c4+2][r] = v.z; As[c4+3][r] = v.w;
        }
        #pragma unroll
        for (int i = 0; i < 2; i++) {
            int c = tid + (i << 7);
            int r = c >> 4, c4 = (c & 15) << 2;
            *(float4*)&Bs[r][c4] = *(const float4*)&B[(size_t)(k0 + r)*N + col0 + c4];
        }
        __syncthreads();
        #pragma unroll
        for (int k = 0; k < 16; k++) {
            float4 a0 = *(const float4*)&As[k][ty << 3];
            float4 a1 = *(const float4*)&As[k][(ty << 3) + 4];
            float4 bv = *(const float4*)&Bs[k][tx << 2];
            float a[8] = {a0.x,a0.y,a0.z,a0.w,a1.x,a1.y,a1.z,a1.w};
            float b[4] = {bv.x,bv.y,bv.z,bv.w};
            #pragma unroll
            for (int ii = 0; ii < 8; ii++)
                #pragma unroll
                for (int jj = 0; jj < 4; jj++)
                    acc[ii][jj] += a[ii] * b[jj];
        }
        __syncthreads();
    }
    #pragma unroll
    for (int ii = 0; ii < 8; ii++) {
        int r = row0 + (ty << 3) + ii;
        int c = col0 + (tx << 2);
        float4 v;
        v.x = acc[ii][0]; v.y = acc[ii][1]; v.z = acc[ii][2]; v.w = acc[ii][3];
        if (MODE == 1) {
            v.x = 2.f*v.x - ((r == c+0) ? 1.f : 0.f);
            v.y = 2.f*v.y - ((r == c+1) ? 1.f : 0.f);
            v.z = 2.f*v.z - ((r == c+2) ? 1.f : 0.f);
            v.w = 2.f*v.w - ((r == c+3) ? 1.f : 0.f);
        }
        *(float4*)&C[(size_t)r*N + c] = v;
    }
}

// ---------------- gate: zr = sigmoid([f6]@Wg + bg); g = z*h; store r ----------
// rows = n*BB+b (16384), cols = 128. K = 384 in 12 chunks of 32.
// chunk source order MUST match W_gate [K=3][2D=128][128] flattening:
//   k0:[x_t | h], k1:[xd1 | hd1], k2:[xd2 | hd2]
__global__ __launch_bounds__(256)
void gate_kernel(const float* __restrict__ Wg, const float* __restrict__ bg, int t) {
    __shared__ float Fs[32][68];    // [k][row], padded
    __shared__ float Ws[32][128];
    int tid  = threadIdx.x;
    int row0 = blockIdx.x << 6;     // 64 rows per block
    int ty = tid >> 4;              // 0..15 -> rows ty*4
    int tx = tid & 15;              // 0..15 -> cols tx*8
    float acc[4][8] = {};

    for (int kc = 0; kc < 12; kc++) {
        int s    = kc >> 1;
        int koff = (kc & 1) << 5;
        const float* src; size_t stride;
        switch (s) {
            case 0: src = g_xT  + (size_t)t*DD; stride = (size_t)TT*DD; break;
            case 1: src = g_h;                  stride = DD;            break;
            case 2: src = g_xd1 + (size_t)t*DD; stride = (size_t)TT*DD; break;
            case 3: src = g_hd1;                stride = DD;            break;
            case 4: src = g_xd2 + (size_t)t*DD; stride = (size_t)TT*DD; break;
            default:src = g_hd2;                stride = DD;            break;
        }
        #pragma unroll
        for (int i = 0; i < 8; i++) {
            int c = tid + (i << 8);           // 0..2047
            int k = c & 31, r = c >> 5;
            Fs[k][r] = src[(size_t)(row0 + r)*stride + koff + k];
        }
        #pragma unroll
        for (int i = 0; i < 4; i++) {
            int c  = tid + (i << 8);          // float4 id 0..1023
            int k  = c >> 5, o4 = (c & 31) << 2;
            *(float4*)&Ws[k][o4] = *(const float4*)&Wg[(size_t)(kc*32 + k)*128 + o4];
        }
        __syncthreads();
        #pragma unroll
        for (int k = 0; k < 32; k++) {
            float4 av = *(const float4*)&Fs[k][ty << 2];
            float4 w0 = *(const float4*)&Ws[k][tx << 3];
            float4 w1 = *(const float4*)&Ws[k][(tx << 3) + 4];
            float a[4] = {av.x, av.y, av.z, av.w};
            float w[8] = {w0.x,w0.y,w0.z,w0.w,w1.x,w1.y,w1.z,w1.w};
            #pragma unroll
            for (int ii = 0; ii < 4; ii++)
                #pragma unroll
                for (int jj = 0; jj < 8; jj++)
                    acc[ii][jj] += a[ii] * w[jj];
        }
        __syncthreads();
    }
    #pragma unroll
    for (int ii = 0; ii < 4; ii++) {
        int r = row0 + (ty << 2) + ii;
        #pragma unroll
        for (int jj = 0; jj < 8; jj++) {
            int o = (tx << 3) + jj;
            float v  = acc[ii][jj] + bg[o];
            float sg = 1.f / (1.f + expf(-v));
            if (o < 64) g_g[(size_t)r*DD + o]        = sg * g_h[(size_t)r*DD + o];
            else        g_r[(size_t)r*DD + (o - 64)] = sg;
        }
    }
}

// ---------------- cand: hc = tanh([f6]@Wc + bc); GRU update; residual out ----
// chunk order: k0:[x_t | g], k1:[xd1 | gd1], k2:[xd2 | gd2]
__global__ __launch_bounds__(256)
void cand_kernel(const float* __restrict__ Wc, const float* __restrict__ bc,
                 const float* __restrict__ x, float* __restrict__ out, int t) {
    __shared__ float Fs[32][68];
    __shared__ float Ws[32][64];
    int tid  = threadIdx.x;
    int row0 = blockIdx.x << 6;
    int ty = tid >> 4;              // rows ty*4
    int tx = tid & 15;              // cols tx*4
    float acc[4][4] = {};

    for (int kc = 0; kc < 12; kc++) {
        int s    = kc >> 1;
        int koff = (kc & 1) << 5;
        const float* src; size_t stride;
        switch (s) {
            case 0: src = g_xT  + (size_t)t*DD; stride = (size_t)TT*DD; break;
            case 1: src = g_g;                  stride = DD;            break;
            case 2: src = g_xd1 + (size_t)t*DD; stride = (size_t)TT*DD; break;
            case 3: src = g_gd1;                stride = DD;            break;
            case 4: src = g_xd2 + (size_t)t*DD; stride = (size_t)TT*DD; break;
            default:src = g_gd2;                stride = DD;            break;
        }
        #pragma unroll
        for (int i = 0; i < 8; i++) {
            int c = tid + (i << 8);
            int k = c & 31, r = c >> 5;
            Fs[k][r] = src[(size_t)(row0 + r)*stride + koff + k];
        }
        #pragma unroll
        for (int i = 0; i < 2; i++) {
            int c  = tid + (i << 8);          // float4 id 0..511
            int k  = c >> 4, o4 = (c & 15) << 2;
            *(float4*)&Ws[k][o4] = *(const float4*)&Wc[(size_t)(kc*32 + k)*64 + o4];
        }
        __syncthreads();
        #pragma unroll
        for (int k = 0; k < 32; k++) {
            float4 av = *(const float4*)&Fs[k][ty << 2];
            float4 wv = *(const float4*)&Ws[k][tx << 2];
            float a[4] = {av.x, av.y, av.z, av.w};
            float w[4] = {wv.x, wv.y, wv.z, wv.w};
            #pragma unroll
            for (int ii = 0; ii < 4; ii++)
                #pragma unroll
                for (int jj = 0; jj < 4; jj++)
                    acc[ii][jj] += a[ii] * w[jj];
        }
        __syncthreads();
    }
    #pragma unroll
    for (int ii = 0; ii < 4; ii++) {
        int r = row0 + (ty << 2) + ii;
        int n = r >> 3, b = r & 7;
        size_t xbase = (((size_t)b*TT + t)*NN + n)*DD;
        #pragma unroll
        for (int jj = 0; jj < 4; jj++) {
            int o = (tx << 2) + jj;
            float hc = tanhf(acc[ii][jj] + bc[o]);
            size_t idx = (size_t)r*DD + o;
            float rg  = g_r[idx];
            float h0v = g_h[idx];
            float hn  = rg * h0v + (1.f - rg) * hc;
            g_h[idx] = hn;                       // in-place: element owned by this thread
            out[xbase + o] = x[xbase + o] + hn;  // residual
        }
    }
}

// ---------------- launch ----------------
extern "C" void kernel_launch(void* const* d_in, const int* in_sizes, int n_in,
                              void* d_out, int out_size) {
    const float* x   = (const float*)d_in[0];
    const float* h0  = (const float*)d_in[1];
    const float* adj = (const float*)d_in[2];
    const float* Wg  = (const float*)d_in[3];
    const float* bg  = (const float*)d_in[4];
    const float* Wc  = (const float*)d_in[5];
    const float* bc  = (const float*)d_in[6];
    float* out = (float*)d_out;

    void *pS2, *pxT, *pxd1, *pxd2, *ph, *phd1, *phd2, *pg, *pgd1, *pgd2;
    cudaGetSymbolAddress(&pS2,  g_S2);
    cudaGetSymbolAddress(&pxT,  g_xT);
    cudaGetSymbolAddress(&pxd1, g_xd1);
    cudaGetSymbolAddress(&pxd2, g_xd2);
    cudaGetSymbolAddress(&ph,   g_h);
    cudaGetSymbolAddress(&phd1, g_hd1);
    cudaGetSymbolAddress(&phd2, g_hd2);
    cudaGetSymbolAddress(&pg,   g_g);
    cudaGetSymbolAddress(&pgd1, g_gd1);
    cudaGetSymbolAddress(&pgd2, g_gd2);

    const size_t total_x = (size_t)BB*TT*NN*DD;     // 12,582,912
    const size_t total_h = (size_t)BB*NN*DD;        // 1,048,576

    transpose_x_kernel<<<(int)((total_x + 255)/256), 256>>>(x);
    init_h_kernel<<<(int)((total_h + 255)/256), 256>>>(h0);

    // S2 = 2*A@A - I
    sgemm64<1><<<dim3(NN/64, NN/64), 128>>>(adj, adj, (float*)pS2, NN, NN, NN);
    // x diffusions (whole sequence at once)
    sgemm64<0><<<dim3(BTD/64, NN/64), 128>>>(adj,          (const float*)pxT, (float*)pxd1, NN, BTD, NN);
    sgemm64<0><<<dim3(BTD/64, NN/64), 128>>>((float*)pS2,  (const float*)pxT, (float*)pxd2, NN, BTD, NN);

    for (int t = 0; t < TT; t++) {
        sgemm64<0><<<dim3(BD/64, NN/64), 128>>>(adj,         (const float*)ph, (float*)phd1, NN, BD, NN);
        sgemm64<0><<<dim3(BD/64, NN/64), 128>>>((float*)pS2, (const float*)ph, (float*)phd2, NN, BD, NN);
        gate_kernel<<<ROWS/64, 256>>>(Wg, bg, t);
        sgemm64<0><<<dim3(BD/64, NN/64), 128>>>(adj,         (const float*)pg, (float*)pgd1, NN, BD, NN);
        sgemm64<0><<<dim3(BD/64, NN/64), 128>>>((float*)pS2, (const float*)pg, (float*)pgd2, NN, BD, NN);
        cand_kernel<<<ROWS/64, 256>>>(Wc, bc, x, out, t);
    }

    write_last_kernel<<<(int)((total_h + 255)/256), 256>>>(out + total_x);
}